// round 7
// baseline (speedup 1.0000x reference)
#include <cuda_runtime.h>
#include <cuda_fp16.h>
#include <cstdint>
#include <cstddef>

// Problem constants
#define S_ 2048
#define B_ 8
#define D_ 1024
#define E_ 8
#define H_ 512
#define T_ (S_*B_)        // 16384 tokens
#define N1_ (E_*H_)       // 4096 concatenated hidden

// ---------------------------------------------------------------------------
// Device scratch
// ---------------------------------------------------------------------------
__device__ __align__(128) __half g_xn [(size_t)T_*D_];    // LN output fp16 [T, D]
__device__ __align__(128) __half g_hg [(size_t)T_*N1_];   // gated hidden fp16 [T, N1]
__device__ __align__(128) __half g_w1h[(size_t)D_*N1_];   // W1cat [D, E*H]  ([K,N] row-major)
__device__ __align__(128) __half g_w2h[(size_t)N1_*D_];   // W2cat [E*H, D]  ([K,N] row-major)
__device__ float g_gates[B_*E_];
__device__ float g_b2g [B_*D_];
__device__ float g_pmax[B_*128*D_];                       // partial max-pool (128 chunks)

// ---------------------------------------------------------------------------
// Merged prologue kernel: grid = 4096(w1) + 4096(w2) + 16384(LN) + 1024(pool)
// block = 256 threads, everything float4-vectorized.
// ---------------------------------------------------------------------------
#define WC1_BLKS 4096
#define WC2_BLKS 4096
#define LN_BLKS  16384
#define POOL_BLKS 1024     // B * 128 chunks of 16 sequence positions
#define PRE_BLKS (WC1_BLKS + WC2_BLKS + LN_BLKS + POOL_BLKS)

__global__ void __launch_bounds__(256)
k_pre(const float* __restrict__ x, const unsigned char* __restrict__ pad,
      const float* __restrict__ lng, const float* __restrict__ lnb,
      const float* __restrict__ w1, const float* __restrict__ w2)
{
    const int bid = blockIdx.x;
    const int tid = threadIdx.x;

    if (bid < WC1_BLKS) {
        // ---- W1 conversion: g_w1h[d*4096 + e*512 + h] = (half)w1[e][d][h]
        const size_t i = (size_t)bid*1024 + (size_t)tid*4;
        const int d = (int)(i >> 12);
        const int j = (int)(i & 4095);
        const int e = j >> 9;
        const int h = j & 511;
        const float4 v = *(const float4*)&w1[((size_t)e << 19) + ((size_t)d << 9) + h];
        __half2 hh[2];
        hh[0] = __floats2half2_rn(v.x, v.y);
        hh[1] = __floats2half2_rn(v.z, v.w);
        *(uint2*)&g_w1h[i] = *(uint2*)hh;
    } else if (bid < WC1_BLKS + WC2_BLKS) {
        // ---- W2 conversion: flat fp32 -> fp16
        const size_t i = (size_t)(bid - WC1_BLKS)*1024 + (size_t)tid*4;
        const float4 v = *(const float4*)&w2[i];
        __half2 hh[2];
        hh[0] = __floats2half2_rn(v.x, v.y);
        hh[1] = __floats2half2_rn(v.z, v.w);
        *(uint2*)&g_w2h[i] = *(uint2*)hh;
    } else if (bid < WC1_BLKS + WC2_BLKS + LN_BLKS) {
        // ---- LayerNorm row -> fp16
        const int t = bid - (WC1_BLKS + WC2_BLKS);
        const float4 v = ((const float4*)(x + (size_t)t*D_))[tid];

        float s  = v.x + v.y + v.z + v.w;
        float ss = v.x*v.x + v.y*v.y + v.z*v.z + v.w*v.w;
        #pragma unroll
        for (int o = 16; o; o >>= 1) {
            s  += __shfl_xor_sync(0xffffffffu, s,  o);
            ss += __shfl_xor_sync(0xffffffffu, ss, o);
        }
        __shared__ float rs[8], rss[8];
        if ((tid & 31) == 0) { rs[tid>>5] = s; rss[tid>>5] = ss; }
        __syncthreads();
        s = 0.f; ss = 0.f;
        #pragma unroll
        for (int w = 0; w < 8; ++w) { s += rs[w]; ss += rss[w]; }

        const float mu  = s * (1.0f / D_);
        const float var = ss * (1.0f / D_) - mu*mu;
        const float inv = rsqrtf(var + 1e-5f);

        const float4 gm = ((const float4*)lng)[tid];
        const float4 bt = ((const float4*)lnb)[tid];
        __half2* dst = (__half2*)(g_xn + (size_t)t*D_ + (size_t)tid*4);
        dst[0] = __floats2half2_rn((v.x - mu)*inv*gm.x + bt.x, (v.y - mu)*inv*gm.y + bt.y);
        dst[1] = __floats2half2_rn((v.z - mu)*inv*gm.z + bt.z, (v.w - mu)*inv*gm.w + bt.w);
    } else {
        // ---- partial masked max-pool: chunk of 16 sequence positions
        const int p  = bid - (WC1_BLKS + WC2_BLKS + LN_BLKS);
        const int b  = p >> 7;
        const int ch = p & 127;
        const int d0 = tid * 4;
        const int s0 = ch * 16;
        float4 m = make_float4(-INFINITY, -INFINITY, -INFINITY, -INFINITY);
        #pragma unroll 4
        for (int i = 0; i < 16; ++i) {
            const int s = s0 + i;
            float4 v = *(const float4*)&x[((size_t)s*B_ + b)*D_ + d0];
            const float neg = pad[b*S_ + s] ? -1e30f : 0.f;
            m.x = fmaxf(m.x, v.x + neg);
            m.y = fmaxf(m.y, v.y + neg);
            m.z = fmaxf(m.z, v.z + neg);
            m.w = fmaxf(m.w, v.w + neg);
        }
        *(float4*)&g_pmax[(size_t)(((b << 7) | ch) << 10) + d0] = m;
    }
}

// ---------------------------------------------------------------------------
// Gate kernel: reduce partials -> logits -> gates -> gate-weighted b2.
// grid B, block 1024
// ---------------------------------------------------------------------------
__global__ void k_gate2(const float* __restrict__ gw, const float* __restrict__ b2,
                        float* __restrict__ logits_out)
{
    const int b = blockIdx.x, d = threadIdx.x;
    float m = -INFINITY;
    #pragma unroll 8
    for (int c = 0; c < 128; ++c) m = fmaxf(m, g_pmax[(size_t)(((b << 7) | c) << 10) + d]);

    __shared__ float red[1024];
    __shared__ float slog[E_];
    __shared__ float sg[E_];
    for (int e = 0; e < E_; ++e) {
        red[d] = m * gw[e*D_ + d];
        __syncthreads();
        for (int off = 512; off > 0; off >>= 1) {
            if (d < off) red[d] += red[d + off];
            __syncthreads();
        }
        if (d == 0) slog[e] = red[0];
        __syncthreads();
    }

    if (d == 0) {
        float mx = -INFINITY;
        #pragma unroll
        for (int e = 0; e < E_; ++e) mx = fmaxf(mx, slog[e]);
        float ex[E_]; float sum = 0.f;
        #pragma unroll
        for (int e = 0; e < E_; ++e) { ex[e] = expf(slog[e] - mx); sum += ex[e]; }
        float t2 = 0.f;
        #pragma unroll
        for (int e = 0; e < E_; ++e) t2 += ex[e] / sum;
        #pragma unroll
        for (int e = 0; e < E_; ++e) {
            float g = (ex[e] / sum) / (t2 + 1e-9f);
            sg[e] = g;
            g_gates[b*E_ + e] = g;
            if (logits_out) logits_out[b*E_ + e] = slog[e];
        }
    }
    __syncthreads();

    float acc = 0.f;
    #pragma unroll
    for (int e = 0; e < E_; ++e) acc += sg[e] * b2[e*D_ + d];
    g_b2g[b*D_ + d] = acc;
}

// ---------------------------------------------------------------------------
// mma.sync GEMM: 128x256x32 CTA tile, 8 warps, 64x64 warp tile,
// 3-stage cp.async pipeline (81.4 KB smem) -> 2 CTAs/SM.
// ---------------------------------------------------------------------------
__device__ __forceinline__ void ldsm4(uint32_t* r, uint32_t a) {
    asm volatile("ldmatrix.sync.aligned.m8n8.x4.shared.b16 {%0,%1,%2,%3},[%4];"
                 : "=r"(r[0]), "=r"(r[1]), "=r"(r[2]), "=r"(r[3]) : "r"(a));
}
__device__ __forceinline__ void ldsm4t(uint32_t& r0, uint32_t& r1, uint32_t& r2, uint32_t& r3, uint32_t a) {
    asm volatile("ldmatrix.sync.aligned.m8n8.x4.trans.shared.b16 {%0,%1,%2,%3},[%4];"
                 : "=r"(r0), "=r"(r1), "=r"(r2), "=r"(r3) : "r"(a));
}
__device__ __forceinline__ void cpa16(uint32_t d, const void* s) {
    asm volatile("cp.async.cg.shared.global [%0],[%1],16;" :: "r"(d), "l"(s));
}
__device__ __forceinline__ void mma_(float* d, const uint32_t* a, const uint32_t* b) {
    asm volatile("mma.sync.aligned.m16n8k16.row.col.f32.f16.f16.f32 "
                 "{%0,%1,%2,%3},{%4,%5,%6,%7},{%8,%9},{%0,%1,%2,%3};"
                 : "+f"(d[0]), "+f"(d[1]), "+f"(d[2]), "+f"(d[3])
                 : "r"(a[0]), "r"(a[1]), "r"(a[2]), "r"(a[3]), "r"(b[0]), "r"(b[1]));
}

#define LDA_ 40            // halfs per A row  (128x32 tile)
#define LDB_ 264           // halfs per B row  (32x256 tile)
#define ASTG (128*LDA_*2)  // 10240 B
#define BSTG (32*LDB_*2)   // 16896 B
#define NSTAGE 3
#define GSMEM_SZ (NSTAGE*(ASTG+BSTG))   // 81408 B

template<int N_TOT, int K, bool EPI1>
__global__ void __launch_bounds__(256, 2)
k_gemm(const float* __restrict__ b1, const float* __restrict__ xres, float* __restrict__ out)
{
    constexpr int KT = K / 32;

    extern __shared__ __align__(128) char dsm[];
    __half* sA = (__half*)dsm;                       // NSTAGE x 128 x LDA_
    __half* sB = (__half*)(dsm + NSTAGE*ASTG);       // NSTAGE x 32  x LDB_

    const __half* __restrict__ A  = EPI1 ? g_xn  : g_hg;
    const __half* __restrict__ Bm = EPI1 ? g_w1h : g_w2h;

    const int tid  = threadIdx.x;
    const int lane = tid & 31;
    const int warp = tid >> 5;
    const int wm = warp >> 2;          // 0..1  (M, 64 rows each)
    const int wn = warp & 3;           // 0..3  (N, 64 cols each)
    const int bm = blockIdx.y * 128;
    const int bn = blockIdx.x * 256;

    float acc[4][8][4];
    #pragma unroll
    for (int i = 0; i < 4; ++i)
        #pragma unroll
        for (int j = 0; j < 8; ++j)
            #pragma unroll
            for (int p = 0; p < 4; ++p) acc[i][j][p] = 0.f;

    const uint32_t sab = (uint32_t)__cvta_generic_to_shared(sA);
    const uint32_t sbb = (uint32_t)__cvta_generic_to_shared(sB);

    auto load_stage = [&](int st, int k0) {
        const uint32_t sa = sab + st*ASTG;
        const uint32_t sb = sbb + st*BSTG;
        #pragma unroll
        for (int t = 0; t < 2; ++t) {            // A: 128 rows x 4 chunks(16B)
            int q = tid + t*256;
            int r = q >> 2, c = q & 3;
            cpa16(sa + (uint32_t)(r*LDA_ + c*8)*2, A + (size_t)(bm + r)*K + k0 + c*8);
        }
        #pragma unroll
        for (int t = 0; t < 4; ++t) {            // B: 32 rows x 32 chunks(16B)
            int q = tid + t*256;
            int r = q >> 5, c = q & 31;
            cpa16(sb + (uint32_t)(r*LDB_ + c*8)*2, Bm + (size_t)(k0 + r)*N_TOT + bn + c*8);
        }
        asm volatile("cp.async.commit_group;");
    };

    auto compute_stage = [&](int st) {
        const uint32_t abase = sab + st*ASTG;
        const uint32_t bbase = sbb + st*BSTG;
        #pragma unroll
        for (int ks = 0; ks < 2; ++ks) {
            const int k0 = ks * 16;
            uint32_t af[4][4], bf[8][2];
            #pragma unroll
            for (int i = 0; i < 4; ++i) {
                int row = wm*64 + i*16 + (lane & 15);
                int col = k0 + ((lane >> 4) << 3);
                ldsm4(af[i], abase + (uint32_t)(row*LDA_ + col)*2);
            }
            #pragma unroll
            for (int jj = 0; jj < 4; ++jj) {
                int kr  = k0 + (lane & 15);
                int col = wn*64 + jj*16 + ((lane >> 4) << 3);
                ldsm4t(bf[2*jj][0], bf[2*jj][1], bf[2*jj+1][0], bf[2*jj+1][1],
                       bbase + (uint32_t)(kr*LDB_ + col)*2);
            }
            #pragma unroll
            for (int i = 0; i < 4; ++i)
                #pragma unroll
                for (int j = 0; j < 8; ++j)
                    mma_(acc[i][j], af[i], bf[j]);
        }
    };

    load_stage(0, 0);
    load_stage(1, 32);
    int st  = 0;                        // stage being computed
    int stl = 2;                        // stage to load next
    for (int it = 0; it < KT; ++it) {
        asm volatile("cp.async.wait_group 1;");
        __syncthreads();
        if (it + 2 < KT) load_stage(stl, (it + 2)*32);
        else             asm volatile("cp.async.commit_group;");
        compute_stage(st);
        st  = (st  == NSTAGE-1) ? 0 : st  + 1;
        stl = (stl == NSTAGE-1) ? 0 : stl + 1;
    }

    // ---- epilogue ----
    const int g  = lane >> 2;
    const int tc = lane & 3;
    if (EPI1) {
        #pragma unroll
        for (int i = 0; i < 4; ++i) {
            #pragma unroll
            for (int j = 0; j < 8; ++j) {
                const int col = bn + wn*64 + j*8 + tc*2;
                const int e = col >> 9;
                const float bb0 = __ldg(&b1[col]), bb1 = __ldg(&b1[col + 1]);
                #pragma unroll
                for (int p = 0; p < 2; ++p) {
                    const int row = bm + wm*64 + i*16 + g + p*8;
                    const float gsc = g_gates[((row & 7) << 3) + e];
                    float v0 = fmaxf(acc[i][j][2*p+0] + bb0, 0.f) * gsc;
                    float v1 = fmaxf(acc[i][j][2*p+1] + bb1, 0.f) * gsc;
                    *reinterpret_cast<__half2*>(&g_hg[(size_t)row*N1_ + col]) =
                        __floats2half2_rn(v0, v1);
                }
            }
        }
    } else {
        #pragma unroll
        for (int i = 0; i < 4; ++i) {
            #pragma unroll
            for (int j = 0; j < 8; ++j) {
                const int col = bn + wn*64 + j*8 + tc*2;
                #pragma unroll
                for (int p = 0; p < 2; ++p) {
                    const int row = bm + wm*64 + i*16 + g + p*8;
                    const size_t o = (size_t)row*D_ + col;
                    const int bo = (row & 7)*D_ + col;
                    float2 r;
                    r.x = acc[i][j][2*p+0] + xres[o]     + g_b2g[bo];
                    r.y = acc[i][j][2*p+1] + xres[o + 1] + g_b2g[bo + 1];
                    *reinterpret_cast<float2*>(&out[o]) = r;
                }
            }
        }
    }
}

// ---------------------------------------------------------------------------
// Launch
// ---------------------------------------------------------------------------
extern "C" void kernel_launch(void* const* d_in, const int* in_sizes, int n_in,
                              void* d_out, int out_size)
{
    const float*         x   = (const float*)d_in[0];
    const unsigned char* pad = (const unsigned char*)d_in[1];
    const float*         gw  = (const float*)d_in[2];
    const float*         lng = (const float*)d_in[3];
    const float*         lnb = (const float*)d_in[4];
    const float*         w1  = (const float*)d_in[5];
    const float*         b1  = (const float*)d_in[6];
    const float*         w2  = (const float*)d_in[7];
    const float*         b2  = (const float*)d_in[8];
    float* out = (float*)d_out;

    float* logits_dst = (out_size >= T_*D_ + B_*E_) ? (out + (size_t)T_*D_) : nullptr;

    static bool attr_done = false;
    if (!attr_done) {
        cudaFuncSetAttribute(k_gemm<N1_, D_,  true >, cudaFuncAttributeMaxDynamicSharedMemorySize, GSMEM_SZ);
        cudaFuncSetAttribute(k_gemm<D_,  N1_, false>, cudaFuncAttributeMaxDynamicSharedMemorySize, GSMEM_SZ);
        attr_done = true;
    }

    k_pre  <<<PRE_BLKS, 256>>>(x, pad, lng, lnb, w1, w2);
    k_gate2<<<B_, 1024>>>(gw, b2, logits_dst);

    // GEMM1: XN[16384,1024] @ W1cat[1024,4096] -> g_hg (relu, +b1, *gate)
    k_gemm<N1_, D_,  true ><<<dim3(N1_/256, T_/128), 256, GSMEM_SZ>>>(b1, nullptr, nullptr);
    // GEMM2: HG[16384,4096] @ W2cat[4096,1024] + x + b2g -> out
    k_gemm<D_,  N1_, false><<<dim3(D_/256,  T_/128), 256, GSMEM_SZ>>>(nullptr, x, out);
}